// round 9
// baseline (speedup 1.0000x reference)
#include <cuda_runtime.h>
#include <math.h>

#define N_NODES 50000
#define N_EDGES 800000
#define F_IN    32
#define H_DIM   64
#define C_OUT   7
#define C_PAD   8
#define BN_EPS  1e-5f

// ---------------- scratch (device globals; no allocation) ----------------
__device__ __align__(128) float  g_Y0[N_NODES * H_DIM];   // x @ W[0]
__device__ __align__(128) float  g_Y1[N_NODES * H_DIM];   // x @ (W[1]-W[0])
__device__ __align__(128) float  g_Z [N_NODES * H_DIM];   // x @ R + B
__device__ __align__(128) float  g_H [N_NODES * H_DIM];   // hidden activations
__device__ __align__(128) float2 g_edge[N_EDGES];         // CSR payload: (src as int bits, u)
__device__ __align__(128) int    g_cnt[N_NODES];          // in-degree histogram
__device__ __align__(128) int    g_off[N_NODES + 1];      // CSR row offsets
__device__ __align__(128) int    g_cur[N_NODES];          // placement cursors

// ---------------- CSR build ----------------
__global__ void zero_cnt_kernel() {
    int i = blockIdx.x * blockDim.x + threadIdx.x;
    if (i < N_NODES) g_cnt[i] = 0;
}

__global__ void deg_kernel(const int* __restrict__ ei) {
    int e = blockIdx.x * blockDim.x + threadIdx.x;
    if (e < N_EDGES) atomicAdd(&g_cnt[ei[N_EDGES + e]], 1);
}

// single-block exclusive scan of g_cnt -> g_off, g_cur
__global__ void __launch_bounds__(1024) scan_kernel() {
    __shared__ int ssum[1024];
    const int NPT = (N_NODES + 1023) / 1024;          // 49
    int t = threadIdx.x;
    int base = t * NPT;

    int local = 0;
    for (int i = 0; i < NPT; i++) {
        int idx = base + i;
        if (idx < N_NODES) local += g_cnt[idx];
    }
    ssum[t] = local;
    __syncthreads();

    // Hillis-Steele inclusive scan
    for (int d = 1; d < 1024; d <<= 1) {
        int v = (t >= d) ? ssum[t - d] : 0;
        __syncthreads();
        ssum[t] += v;
        __syncthreads();
    }

    int run = (t > 0) ? ssum[t - 1] : 0;              // exclusive prefix
    for (int i = 0; i < NPT; i++) {
        int idx = base + i;
        if (idx < N_NODES) {
            g_off[idx] = run;
            g_cur[idx] = run;
            run += g_cnt[idx];
        }
    }
    if (t == 0) g_off[N_NODES] = ssum[1023];
}

__global__ void build_kernel(const int* __restrict__ ei, const float* __restrict__ ea) {
    int e = blockIdx.x * blockDim.x + threadIdx.x;
    if (e >= N_EDGES) return;
    int s = ei[e];
    int d = ei[N_EDGES + e];
    int p = atomicAdd(&g_cur[d], 1);
    g_edge[p] = make_float2(__int_as_float(s), ea[e]);
}

// ---------------- fused node-side GEMM: Y0 = X@W0, Y1 = X@(W1-W0), Z = X@R + B ----------------
template<int CIN, int COUT, int COUTP, int NT>
__global__ void __launch_bounds__(256)
gemm3_kernel(const float* __restrict__ Xext,
             const float* __restrict__ W,     // [2][CIN][COUT]
             const float* __restrict__ R,     // [CIN][COUT]
             const float* __restrict__ B,     // [COUT]
             int use_h)
{
    constexpr int TY    = 256 / COUTP;
    constexpr int NODES = TY * NT;
    __shared__ float sx[NODES][CIN];

    const float* X = use_h ? (const float*)g_H : Xext;

    int nbase_blk = blockIdx.x * NODES;
    int tid = threadIdx.y * COUTP + threadIdx.x;

    constexpr int NV = NODES * CIN / 4;
    const float4* X4 = reinterpret_cast<const float4*>(X);
    float4* sx4 = reinterpret_cast<float4*>(&sx[0][0]);
    #pragma unroll
    for (int i = tid; i < NV; i += 256) {
        int nn = nbase_blk + i / (CIN / 4);
        float4 v = make_float4(0.f, 0.f, 0.f, 0.f);
        if (nn < N_NODES) v = X4[nn * (CIN / 4) + (i % (CIN / 4))];
        sx4[i] = v;
    }
    __syncthreads();

    int o  = threadIdx.x;
    int nb = threadIdx.y * NT;

    float a0[NT], a1[NT], az[NT];
    #pragma unroll
    for (int j = 0; j < NT; j++) { a0[j] = 0.f; a1[j] = 0.f; az[j] = 0.f; }

    float b = 0.f;
    if (o < COUT) {
        b = B[o];
        #pragma unroll 4
        for (int c = 0; c < CIN; c++) {
            float w0 = W[c * COUT + o];
            float w1 = W[CIN * COUT + c * COUT + o];
            float r  = R[c * COUT + o];
            float dw = w1 - w0;
            #pragma unroll
            for (int j = 0; j < NT; j++) {
                float xv = sx[nb + j][c];
                a0[j] = fmaf(xv, w0, a0[j]);
                a1[j] = fmaf(xv, dw, a1[j]);
                az[j] = fmaf(xv, r,  az[j]);
            }
        }
    }

    #pragma unroll
    for (int j = 0; j < NT; j++) {
        int n = nbase_blk + nb + j;
        if (n < N_NODES) {
            g_Y0[n * COUTP + o] = a0[j];
            g_Y1[n * COUTP + o] = a1[j];
            g_Z [n * COUTP + o] = az[j] + b;   // pad columns get exact 0
        }
    }
}

// ---------------- gather aggregation + mean + residual + BN + ELU (H=64) ----------------
// one warp per destination node; each lane owns 2 channels
__global__ void __launch_bounds__(256)
agg_bn_kernel(const float* __restrict__ G,  const float* __restrict__ BE,
              const float* __restrict__ RM, const float* __restrict__ RV)
{
    int gw   = (blockIdx.x * blockDim.x + threadIdx.x) >> 5;
    int lane = threadIdx.x & 31;
    if (gw >= N_NODES) return;

    int beg = g_off[gw];
    int end = g_off[gw + 1];

    const float2* Y0 = reinterpret_cast<const float2*>(g_Y0);
    const float2* Y1 = reinterpret_cast<const float2*>(g_Y1);

    float ax = 0.f, ay = 0.f;
    #pragma unroll 4
    for (int e = beg; e < end; e++) {
        float2 rec = g_edge[e];                 // broadcast across the warp
        int   s = __float_as_int(rec.x);
        float u = rec.y;
        float2 v0 = Y0[s * 32 + lane];
        float2 v1 = Y1[s * 32 + lane];
        ax += fmaf(u, v1.x, v0.x);
        ay += fmaf(u, v1.y, v0.y);
    }

    int deg = end - beg;
    float inv = 1.f / (float)(deg < 1 ? 1 : deg);

    int o = lane * 2;
    const float2* Z2 = reinterpret_cast<const float2*>(g_Z);
    float2 z  = Z2[gw * 32 + lane];
    float2 g  = reinterpret_cast<const float2*>(G )[lane];
    float2 be = reinterpret_cast<const float2*>(BE)[lane];
    float2 rm = reinterpret_cast<const float2*>(RM)[lane];
    float2 rv = reinterpret_cast<const float2*>(RV)[lane];

    float vx = ax * inv + z.x;
    float vy = ay * inv + z.y;
    vx = (vx - rm.x) * rsqrtf(rv.x + BN_EPS) * g.x + be.x;
    vy = (vy - rm.y) * rsqrtf(rv.y + BN_EPS) * g.y + be.y;
    vx = (vx > 0.f) ? vx : expm1f(vx);
    vy = (vy > 0.f) ? vy : expm1f(vy);

    reinterpret_cast<float2*>(g_H)[gw * 32 + lane] = make_float2(vx, vy);
    (void)o;
}

// ---------------- final: gather agg + mean + residual + log_softmax (C=7, pad 8) ----------------
// 8 lanes per node; shuffle-based reduction within the 8-lane group
__global__ void __launch_bounds__(256)
agg_final_kernel(float* __restrict__ out)
{
    int t    = blockIdx.x * blockDim.x + threadIdx.x;
    int node = t >> 3;
    int o    = t & 7;
    if (node >= N_NODES) return;

    int beg = g_off[node];
    int end = g_off[node + 1];

    float acc = 0.f;
    #pragma unroll 4
    for (int e = beg; e < end; e++) {
        float2 rec = g_edge[e];                 // broadcast across 8-lane group
        int   s = __float_as_int(rec.x);
        float u = rec.y;
        acc += fmaf(u, g_Y1[s * C_PAD + o], g_Y0[s * C_PAD + o]);
    }

    int deg = end - beg;
    float inv = 1.f / (float)(deg < 1 ? 1 : deg);
    float v = acc * inv + g_Z[node * C_PAD + o];

    float vm = (o < C_OUT) ? v : -INFINITY;
    float mx = vm;
    #pragma unroll
    for (int d = 1; d < 8; d <<= 1)
        mx = fmaxf(mx, __shfl_xor_sync(0xFFFFFFFFu, mx, d));

    float ex = (o < C_OUT) ? __expf(v - mx) : 0.f;
    float s  = ex;
    #pragma unroll
    for (int d = 1; d < 8; d <<= 1)
        s += __shfl_xor_sync(0xFFFFFFFFu, s, d);

    float lse = mx + logf(s);
    if (o < C_OUT) out[node * C_OUT + o] = v - lse;
}

// ---------------- launch ----------------
extern "C" void kernel_launch(void* const* d_in, const int* in_sizes, int n_in,
                              void* d_out, int out_size)
{
    const float* x   = (const float*)d_in[0];
    const int*   ei  = (const int*)  d_in[1];
    const float* ea  = (const float*)d_in[2];
    const float* W0  = (const float*)d_in[3];
    const float* R0  = (const float*)d_in[4];
    const float* B0  = (const float*)d_in[5];
    const float* W1  = (const float*)d_in[6];
    const float* R1  = (const float*)d_in[7];
    const float* B1  = (const float*)d_in[8];
    const float* W2  = (const float*)d_in[9];
    const float* R2  = (const float*)d_in[10];
    const float* B2  = (const float*)d_in[11];
    const float* G0  = (const float*)d_in[12];
    const float* BE0 = (const float*)d_in[13];
    const float* RM0 = (const float*)d_in[14];
    const float* RV0 = (const float*)d_in[15];
    const float* G1  = (const float*)d_in[16];
    const float* BE1 = (const float*)d_in[17];
    const float* RM1 = (const float*)d_in[18];
    const float* RV1 = (const float*)d_in[19];
    float* out = (float*)d_out;

    // ---- CSR build (once; reused by all 3 layers) ----
    zero_cnt_kernel<<<(N_NODES + 255) / 256, 256>>>();
    deg_kernel<<<(N_EDGES + 255) / 256, 256>>>(ei);
    scan_kernel<<<1, 1024>>>();
    build_kernel<<<(N_EDGES + 255) / 256, 256>>>(ei, ea);

    // ---- Layer 0: F_IN=32 -> H=64 ----
    gemm3_kernel<32, 64, 64, 8><<<(N_NODES + 31) / 32, dim3(64, 4)>>>(x, W0, R0, B0, 0);
    agg_bn_kernel<<<(N_NODES * 32 + 255) / 256, 256>>>(G0, BE0, RM0, RV0);

    // ---- Layer 1: H=64 -> H=64 ----
    gemm3_kernel<64, 64, 64, 8><<<(N_NODES + 31) / 32, dim3(64, 4)>>>(nullptr, W1, R1, B1, 1);
    agg_bn_kernel<<<(N_NODES * 32 + 255) / 256, 256>>>(G1, BE1, RM1, RV1);

    // ---- Layer 2: H=64 -> C=7 (padded to 8) ----
    gemm3_kernel<64, 7, 8, 2><<<(N_NODES + 63) / 64, dim3(8, 32)>>>(nullptr, W2, R2, B2, 1);
    agg_final_kernel<<<(N_NODES * 8 + 255) / 256, 256>>>(out);
}